// round 6
// baseline (speedup 1.0000x reference)
#include <cuda_runtime.h>
#include <cuda_bf16.h>
#include <cstdint>

// WeightedSumSessEmbedding: sparse COO [16384 x 1M] @ emb[1M x 64]
// NNZ=819200, row_idx sorted. Inputs: row_idx[i32], col_idx[i32],
// data[f32], num_ids[i32 scalar], embeddings[f32 1M*64]. Output f32 [16384*64].
//
// Two col-partitioned passes: each pass gathers only embedding rows in a
// ~128MB slice of the table, so the per-pass unique working set (~72MB)
// fits in L2 and duplicate column accesses become L2 hits.

#define EMB_DIM 64
#define CHUNK 64             // nnz per warp  -> 12800 warps total
#define THREADS 256          // 8 warps per block
#define UNROLL 16
#define NPASS 2

__global__ void __launch_bounds__(THREADS, 4)   // 64-reg budget: 16 gathers live
weighted_seg_sum_kernel(const int* __restrict__ row_idx,
                        const int* __restrict__ col_idx,
                        const float* __restrict__ data,
                        const float* __restrict__ emb,
                        float* __restrict__ out,
                        int nnz, int col_lo, int col_hi)
{
    const int warp = (blockIdx.x * blockDim.x + threadIdx.x) >> 5;
    const int lane = threadIdx.x & 31;

    const int start = warp * CHUNK;
    if (start >= nnz) return;
    const int end = min(start + CHUNK, nnz);

    const unsigned lo   = (unsigned)col_lo;
    const unsigned span = (unsigned)(col_hi - col_lo);

    // Each lane owns two consecutive dims via float2: [2*lane, 2*lane+1].
    const float2* __restrict__ emb2 = reinterpret_cast<const float2*>(emb);

    float2 acc = make_float2(0.0f, 0.0f);
    int cur_row = __ldg(&row_idx[start]);

    #define FLUSH()                                                          \
        do {                                                                 \
            float* o = out + (size_t)cur_row * EMB_DIM + 2 * lane;           \
            atomicAdd(o,     acc.x);                                         \
            atomicAdd(o + 1, acc.y);                                         \
            acc.x = 0.0f; acc.y = 0.0f;                                      \
        } while (0)

    // Filtered entries carry e = {0,0}: flush logic unchanged, contributes 0.
    #define STEP(r, w, e)                                                    \
        do {                                                                 \
            if ((r) != cur_row) { FLUSH(); cur_row = (r); }                  \
            acc.x = fmaf((w), (e).x, acc.x);                                 \
            acc.y = fmaf((w), (e).y, acc.y);                                 \
        } while (0)

    int i = start;
    for (; i + UNROLL <= end; i += UNROLL) {
        const int4 c0 = __ldg(reinterpret_cast<const int4*>(col_idx + i));
        const int4 c1 = __ldg(reinterpret_cast<const int4*>(col_idx + i + 4));
        const int4 c2 = __ldg(reinterpret_cast<const int4*>(col_idx + i + 8));
        const int4 c3 = __ldg(reinterpret_cast<const int4*>(col_idx + i + 12));
        const int cols[UNROLL] = {c0.x, c0.y, c0.z, c0.w,
                                  c1.x, c1.y, c1.z, c1.w,
                                  c2.x, c2.y, c2.z, c2.w,
                                  c3.x, c3.y, c3.z, c3.w};

        // Predicated gathers: warp-uniform condition -> no traffic when off.
        float2 e[UNROLL];
        #pragma unroll
        for (int j = 0; j < UNROLL; ++j) {
            e[j] = make_float2(0.0f, 0.0f);
            if ((unsigned)cols[j] - lo < span)
                e[j] = __ldg(emb2 + (size_t)cols[j] * 32 + lane);
        }

        const int4 r0 = __ldg(reinterpret_cast<const int4*>(row_idx + i));
        const int4 r1 = __ldg(reinterpret_cast<const int4*>(row_idx + i + 4));
        const int4 r2 = __ldg(reinterpret_cast<const int4*>(row_idx + i + 8));
        const int4 r3 = __ldg(reinterpret_cast<const int4*>(row_idx + i + 12));
        const float4 w0 = __ldg(reinterpret_cast<const float4*>(data + i));
        const float4 w1 = __ldg(reinterpret_cast<const float4*>(data + i + 4));
        const float4 w2 = __ldg(reinterpret_cast<const float4*>(data + i + 8));
        const float4 w3 = __ldg(reinterpret_cast<const float4*>(data + i + 12));
        const int rows[UNROLL] = {r0.x, r0.y, r0.z, r0.w,
                                  r1.x, r1.y, r1.z, r1.w,
                                  r2.x, r2.y, r2.z, r2.w,
                                  r3.x, r3.y, r3.z, r3.w};
        const float wts[UNROLL] = {w0.x, w0.y, w0.z, w0.w,
                                   w1.x, w1.y, w1.z, w1.w,
                                   w2.x, w2.y, w2.z, w2.w,
                                   w3.x, w3.y, w3.z, w3.w};

        #pragma unroll
        for (int j = 0; j < UNROLL; ++j)
            STEP(rows[j], wts[j], e[j]);
    }
    // Tail (NNZ is a multiple of 16; kept for generality).
    for (; i < end; ++i) {
        const int   r = __ldg(&row_idx[i]);
        const int   c = __ldg(&col_idx[i]);
        const float w = __ldg(&data[i]);
        float2 e = make_float2(0.0f, 0.0f);
        if ((unsigned)c - lo < span)
            e = __ldg(emb2 + (size_t)c * 32 + lane);
        STEP(r, w, e);
    }

    FLUSH();

    #undef STEP
    #undef FLUSH
}

extern "C" void kernel_launch(void* const* d_in, const int* in_sizes, int n_in,
                              void* d_out, int out_size)
{
    const int*   row_idx = (const int*)  d_in[0];
    const int*   col_idx = (const int*)  d_in[1];
    const float* data    = (const float*)d_in[2];
    const float* emb     = (const float*)d_in[4];
    float*       out     = (float*)d_out;

    const int nnz   = in_sizes[0];
    const int items = in_sizes[4] / EMB_DIM;   // 1,000,000

    cudaMemsetAsync(out, 0, (size_t)out_size * sizeof(float));

    const int warps  = (nnz + CHUNK - 1) / CHUNK;
    const int blocks = (warps * 32 + THREADS - 1) / THREADS;

    const int slice = (items + NPASS - 1) / NPASS;
    for (int p = 0; p < NPASS; ++p) {
        const int lo = p * slice;
        const int hi = min(items, lo + slice);
        weighted_seg_sum_kernel<<<blocks, THREADS>>>(
            row_idx, col_idx, data, emb, out, nnz, lo, hi);
    }
}

// round 7
// speedup vs baseline: 1.1066x; 1.1066x over previous
#include <cuda_runtime.h>
#include <cuda_bf16.h>
#include <cstdint>

// WeightedSumSessEmbedding: sparse COO [16384 x 1M] @ emb[1M x 64]
// NNZ=819200, row_idx sorted. Inputs: row_idx[i32], col_idx[i32],
// data[f32], num_ids[i32 scalar], embeddings[f32 1M*64]. Output f32 [16384*64].
//
// One warp per output row: binary-search the sorted row_idx for this row's
// nnz range, gather+accumulate in registers, single vectorized store.
// No atomics, no output memset, no per-step row compare.

#define EMB_DIM 64
#define THREADS 256           // 8 warps (= 8 rows) per block
#define WARPS_PB (THREADS / 32)

__device__ __forceinline__ int lower_bound(const int* __restrict__ a, int n, int v)
{
    int lo = 0, hi = n;
    while (lo < hi) {
        int m = (lo + hi) >> 1;
        if (__ldg(a + m) < v) lo = m + 1; else hi = m;
    }
    return lo;
}

__global__ void __launch_bounds__(THREADS, 5)   // ~51-reg budget
row_per_warp_kernel(const int* __restrict__ row_idx,
                    const int* __restrict__ col_idx,
                    const float* __restrict__ data,
                    const float* __restrict__ emb,
                    float2* __restrict__ out2,   // out viewed as [nrows][32] float2
                    int nnz, int nrows)
{
    const int row  = blockIdx.x * WARPS_PB + (threadIdx.x >> 5);
    const int lane = threadIdx.x & 31;
    if (row >= nrows) return;

    // nnz range of this row (all lanes redundantly: broadcast loads, L2-hot).
    const int lo = lower_bound(row_idx, nnz, row);
    const int hi = lower_bound(row_idx, nnz, row + 1);

    const float2* __restrict__ emb2 = reinterpret_cast<const float2*>(emb);

    float2 acc = make_float2(0.0f, 0.0f);
    const unsigned FULL = 0xffffffffu;

    for (int base = lo; base < hi; base += 32) {
        const int n = min(32, hi - base);
        // Lane-cooperative coalesced loads of up to 32 (col, weight) pairs.
        const int   cv = (lane < n) ? __ldg(col_idx + base + lane) : 0;
        const float wv = (lane < n) ? __ldg(data    + base + lane) : 0.0f;

        int k = 0;
        // Unroll 8: distribute indices via shfl, issue 8 independent 256B
        // gathers before any consumer.
        for (; k + 8 <= n; k += 8) {
            const int c0 = __shfl_sync(FULL, cv, k + 0);
            const int c1 = __shfl_sync(FULL, cv, k + 1);
            const int c2 = __shfl_sync(FULL, cv, k + 2);
            const int c3 = __shfl_sync(FULL, cv, k + 3);
            const int c4 = __shfl_sync(FULL, cv, k + 4);
            const int c5 = __shfl_sync(FULL, cv, k + 5);
            const int c6 = __shfl_sync(FULL, cv, k + 6);
            const int c7 = __shfl_sync(FULL, cv, k + 7);

            const float2 e0 = __ldg(emb2 + (size_t)c0 * 32 + lane);
            const float2 e1 = __ldg(emb2 + (size_t)c1 * 32 + lane);
            const float2 e2 = __ldg(emb2 + (size_t)c2 * 32 + lane);
            const float2 e3 = __ldg(emb2 + (size_t)c3 * 32 + lane);
            const float2 e4 = __ldg(emb2 + (size_t)c4 * 32 + lane);
            const float2 e5 = __ldg(emb2 + (size_t)c5 * 32 + lane);
            const float2 e6 = __ldg(emb2 + (size_t)c6 * 32 + lane);
            const float2 e7 = __ldg(emb2 + (size_t)c7 * 32 + lane);

            const float w0 = __shfl_sync(FULL, wv, k + 0);
            const float w1 = __shfl_sync(FULL, wv, k + 1);
            const float w2 = __shfl_sync(FULL, wv, k + 2);
            const float w3 = __shfl_sync(FULL, wv, k + 3);
            const float w4 = __shfl_sync(FULL, wv, k + 4);
            const float w5 = __shfl_sync(FULL, wv, k + 5);
            const float w6 = __shfl_sync(FULL, wv, k + 6);
            const float w7 = __shfl_sync(FULL, wv, k + 7);

            acc.x = fmaf(w0, e0.x, acc.x); acc.y = fmaf(w0, e0.y, acc.y);
            acc.x = fmaf(w1, e1.x, acc.x); acc.y = fmaf(w1, e1.y, acc.y);
            acc.x = fmaf(w2, e2.x, acc.x); acc.y = fmaf(w2, e2.y, acc.y);
            acc.x = fmaf(w3, e3.x, acc.x); acc.y = fmaf(w3, e3.y, acc.y);
            acc.x = fmaf(w4, e4.x, acc.x); acc.y = fmaf(w4, e4.y, acc.y);
            acc.x = fmaf(w5, e5.x, acc.x); acc.y = fmaf(w5, e5.y, acc.y);
            acc.x = fmaf(w6, e6.x, acc.x); acc.y = fmaf(w6, e6.y, acc.y);
            acc.x = fmaf(w7, e7.x, acc.x); acc.y = fmaf(w7, e7.y, acc.y);
        }
        // Scalar tail within this 32-batch (warp-uniform trip count).
        for (; k < n; ++k) {
            const int   c = __shfl_sync(FULL, cv, k);
            const float w = __shfl_sync(FULL, wv, k);
            const float2 e = __ldg(emb2 + (size_t)c * 32 + lane);
            acc.x = fmaf(w, e.x, acc.x);
            acc.y = fmaf(w, e.y, acc.y);
        }
    }

    // Single owner per row: plain vectorized store (also covers empty rows).
    out2[(size_t)row * 32 + lane] = acc;
}

extern "C" void kernel_launch(void* const* d_in, const int* in_sizes, int n_in,
                              void* d_out, int out_size)
{
    const int*   row_idx = (const int*)  d_in[0];
    const int*   col_idx = (const int*)  d_in[1];
    const float* data    = (const float*)d_in[2];
    const float* emb     = (const float*)d_in[4];
    float2*      out2    = (float2*)d_out;

    const int nnz   = in_sizes[0];
    const int nrows = out_size / EMB_DIM;   // 16384

    const int blocks = (nrows + WARPS_PB - 1) / WARPS_PB;
    row_per_warp_kernel<<<blocks, THREADS>>>(
        row_idx, col_idx, data, emb, out2, nnz, nrows);
}

// round 8
// speedup vs baseline: 1.2597x; 1.1383x over previous
#include <cuda_runtime.h>
#include <cuda_bf16.h>
#include <cstdint>

// WeightedSumSessEmbedding: sparse COO [16384 x 1M] @ emb[1M x 64]
// NNZ=819200, row_idx sorted. Inputs: row_idx[i32], col_idx[i32],
// data[f32], num_ids[i32 scalar], embeddings[f32 1M*64]. Output f32 [16384*64].
//
// R4 structure (register-path MLP=16 gathers) with:
//  - CHUNK 32: 25600 warps -> finer wave granularity, smaller ragged tail
//  - __ldcs (evict-first) on streaming index/weight reads: keeps L2 for
//    the embedding table (unique footprint ~143MB vs 126MB L2 - marginal)

#define EMB_DIM 64
#define CHUNK 32             // nnz per warp  -> 25600 warps total
#define THREADS 256          // 8 warps per block
#define UNROLL 16

__global__ void __launch_bounds__(THREADS, 4)   // 64-reg budget: 16 gathers live
weighted_seg_sum_kernel(const int* __restrict__ row_idx,
                        const int* __restrict__ col_idx,
                        const float* __restrict__ data,
                        const float* __restrict__ emb,
                        float* __restrict__ out,
                        int nnz)
{
    const int warp = (blockIdx.x * blockDim.x + threadIdx.x) >> 5;
    const int lane = threadIdx.x & 31;

    const int start = warp * CHUNK;
    if (start >= nnz) return;
    const int end = min(start + CHUNK, nnz);

    // Each lane owns two consecutive dims via float2: [2*lane, 2*lane+1].
    const float2* __restrict__ emb2 = reinterpret_cast<const float2*>(emb);

    float2 acc = make_float2(0.0f, 0.0f);
    int cur_row = __ldcs(&row_idx[start]);

    #define FLUSH()                                                          \
        do {                                                                 \
            float* o = out + (size_t)cur_row * EMB_DIM + 2 * lane;           \
            atomicAdd(o,     acc.x);                                         \
            atomicAdd(o + 1, acc.y);                                         \
            acc.x = 0.0f; acc.y = 0.0f;                                      \
        } while (0)

    #define STEP(r, w, e)                                                    \
        do {                                                                 \
            if ((r) != cur_row) { FLUSH(); cur_row = (r); }                  \
            acc.x = fmaf((w), (e).x, acc.x);                                 \
            acc.y = fmaf((w), (e).y, acc.y);                                 \
        } while (0)

    int i = start;
    // Unroll 16: all 16 independent 256B gathers issued before any consumer.
    for (; i + UNROLL <= end; i += UNROLL) {
        const int4 c0 = __ldcs(reinterpret_cast<const int4*>(col_idx + i));
        const int4 c1 = __ldcs(reinterpret_cast<const int4*>(col_idx + i + 4));
        const int4 c2 = __ldcs(reinterpret_cast<const int4*>(col_idx + i + 8));
        const int4 c3 = __ldcs(reinterpret_cast<const int4*>(col_idx + i + 12));
        const int cols[UNROLL] = {c0.x, c0.y, c0.z, c0.w,
                                  c1.x, c1.y, c1.z, c1.w,
                                  c2.x, c2.y, c2.z, c2.w,
                                  c3.x, c3.y, c3.z, c3.w};

        float2 e[UNROLL];
        #pragma unroll
        for (int j = 0; j < UNROLL; ++j)
            e[j] = __ldg(emb2 + (size_t)cols[j] * 32 + lane);

        const int4 r0 = __ldcs(reinterpret_cast<const int4*>(row_idx + i));
        const int4 r1 = __ldcs(reinterpret_cast<const int4*>(row_idx + i + 4));
        const int4 r2 = __ldcs(reinterpret_cast<const int4*>(row_idx + i + 8));
        const int4 r3 = __ldcs(reinterpret_cast<const int4*>(row_idx + i + 12));
        const float4 w0 = __ldcs(reinterpret_cast<const float4*>(data + i));
        const float4 w1 = __ldcs(reinterpret_cast<const float4*>(data + i + 4));
        const float4 w2 = __ldcs(reinterpret_cast<const float4*>(data + i + 8));
        const float4 w3 = __ldcs(reinterpret_cast<const float4*>(data + i + 12));
        const int rows[UNROLL] = {r0.x, r0.y, r0.z, r0.w,
                                  r1.x, r1.y, r1.z, r1.w,
                                  r2.x, r2.y, r2.z, r2.w,
                                  r3.x, r3.y, r3.z, r3.w};
        const float wts[UNROLL] = {w0.x, w0.y, w0.z, w0.w,
                                   w1.x, w1.y, w1.z, w1.w,
                                   w2.x, w2.y, w2.z, w2.w,
                                   w3.x, w3.y, w3.z, w3.w};

        #pragma unroll
        for (int j = 0; j < UNROLL; ++j)
            STEP(rows[j], wts[j], e[j]);
    }
    // Tail (NNZ is a multiple of 16; kept for generality).
    for (; i < end; ++i) {
        const int   r = __ldcs(&row_idx[i]);
        const int   c = __ldcs(&col_idx[i]);
        const float w = __ldcs(&data[i]);
        const float2 e = __ldg(emb2 + (size_t)c * 32 + lane);
        STEP(r, w, e);
    }

    FLUSH();

    #undef STEP
    #undef FLUSH
}

extern "C" void kernel_launch(void* const* d_in, const int* in_sizes, int n_in,
                              void* d_out, int out_size)
{
    const int*   row_idx = (const int*)  d_in[0];
    const int*   col_idx = (const int*)  d_in[1];
    const float* data    = (const float*)d_in[2];
    const float* emb     = (const float*)d_in[4];
    float*       out     = (float*)d_out;

    const int nnz = in_sizes[0];

    cudaMemsetAsync(out, 0, (size_t)out_size * sizeof(float));

    const int warps  = (nnz + CHUNK - 1) / CHUNK;
    const int blocks = (warps * 32 + THREADS - 1) / THREADS;
    weighted_seg_sum_kernel<<<blocks, THREADS>>>(
        row_idx, col_idx, data, emb, out, nnz);
}

// round 9
// speedup vs baseline: 1.4325x; 1.1372x over previous
#include <cuda_runtime.h>
#include <cuda_bf16.h>
#include <cstdint>

// WeightedSumSessEmbedding: sparse COO [16384 x 1M] @ emb[1M x 64]
// NNZ=819200, row_idx sorted. Inputs: row_idx[i32], col_idx[i32],
// data[f32], num_ids[i32 scalar], embeddings[f32 1M*64]. Output f32 [16384*64].
//
// R4 structure (MLP=16 register gathers, CHUNK=64/warp) + SMEM index staging:
// the block cooperatively stages its 512 nnz of (row,col,weight) into SMEM,
// so per-iteration index fetches are 29-cyc LDS broadcasts instead of
// ~600-cyc DRAM loads -> gather pipeline duty cycle ~50% -> ~90%.

#define EMB_DIM 64
#define CHUNK 64                       // nnz per warp
#define THREADS 256                    // 8 warps per block
#define WARPS_PB (THREADS / 32)
#define NNZ_PB (WARPS_PB * CHUNK)      // 512 nnz per block
#define UNROLL 16

__global__ void __launch_bounds__(THREADS, 4)   // 64-reg budget: 16 gathers live
weighted_seg_sum_kernel(const int* __restrict__ row_idx,
                        const int* __restrict__ col_idx,
                        const float* __restrict__ data,
                        const float* __restrict__ emb,
                        float* __restrict__ out,
                        int nnz)
{
    __shared__ int   s_row[NNZ_PB];
    __shared__ int   s_col[NNZ_PB];
    __shared__ float s_w[NNZ_PB];

    const int lane     = threadIdx.x & 31;
    const int wl       = threadIdx.x >> 5;
    const int blk_base = blockIdx.x * NNZ_PB;

    // ---- cooperative index staging: 512 x 12B, fully coalesced ----
    #pragma unroll
    for (int t = threadIdx.x; t < NNZ_PB; t += THREADS) {
        const int g = blk_base + t;
        if (g < nnz) {
            s_row[t] = row_idx[g];
            s_col[t] = col_idx[g];
            s_w[t]   = data[g];
        }
    }
    __syncthreads();

    const int start = blk_base + wl * CHUNK;          // global
    if (start >= nnz) return;
    const int end   = min(start + CHUNK, nnz);
    const int l0    = wl * CHUNK;                     // local (smem) offset

    // Each lane owns two consecutive dims via float2: [2*lane, 2*lane+1].
    const float2* __restrict__ emb2 = reinterpret_cast<const float2*>(emb);

    float2 acc = make_float2(0.0f, 0.0f);
    int cur_row = s_row[l0];

    #define FLUSH()                                                          \
        do {                                                                 \
            float* o = out + (size_t)cur_row * EMB_DIM + 2 * lane;           \
            atomicAdd(o,     acc.x);                                         \
            atomicAdd(o + 1, acc.y);                                         \
            acc.x = 0.0f; acc.y = 0.0f;                                      \
        } while (0)

    #define STEP(r, w, e)                                                    \
        do {                                                                 \
            if ((r) != cur_row) { FLUSH(); cur_row = (r); }                  \
            acc.x = fmaf((w), (e).x, acc.x);                                 \
            acc.y = fmaf((w), (e).y, acc.y);                                 \
        } while (0)

    int li = l0;
    const int lend_main = l0 + ((end - start) & ~(UNROLL - 1));
    const int lend      = l0 + (end - start);

    for (; li < lend_main; li += UNROLL) {
        // 29-cyc broadcast LDS.128s — off the DRAM critical path.
        const int4 c0 = *reinterpret_cast<const int4*>(s_col + li);
        const int4 c1 = *reinterpret_cast<const int4*>(s_col + li + 4);
        const int4 c2 = *reinterpret_cast<const int4*>(s_col + li + 8);
        const int4 c3 = *reinterpret_cast<const int4*>(s_col + li + 12);
        const int cols[UNROLL] = {c0.x, c0.y, c0.z, c0.w,
                                  c1.x, c1.y, c1.z, c1.w,
                                  c2.x, c2.y, c2.z, c2.w,
                                  c3.x, c3.y, c3.z, c3.w};

        // 16 independent 256B gathers in flight before any consumer.
        float2 e[UNROLL];
        #pragma unroll
        for (int j = 0; j < UNROLL; ++j)
            e[j] = __ldg(emb2 + (size_t)cols[j] * 32 + lane);

        const int4 r0 = *reinterpret_cast<const int4*>(s_row + li);
        const int4 r1 = *reinterpret_cast<const int4*>(s_row + li + 4);
        const int4 r2 = *reinterpret_cast<const int4*>(s_row + li + 8);
        const int4 r3 = *reinterpret_cast<const int4*>(s_row + li + 12);
        const float4 w0 = *reinterpret_cast<const float4*>(s_w + li);
        const float4 w1 = *reinterpret_cast<const float4*>(s_w + li + 4);
        const float4 w2 = *reinterpret_cast<const float4*>(s_w + li + 8);
        const float4 w3 = *reinterpret_cast<const float4*>(s_w + li + 12);
        const int rows[UNROLL] = {r0.x, r0.y, r0.z, r0.w,
                                  r1.x, r1.y, r1.z, r1.w,
                                  r2.x, r2.y, r2.z, r2.w,
                                  r3.x, r3.y, r3.z, r3.w};
        const float wts[UNROLL] = {w0.x, w0.y, w0.z, w0.w,
                                   w1.x, w1.y, w1.z, w1.w,
                                   w2.x, w2.y, w2.z, w2.w,
                                   w3.x, w3.y, w3.z, w3.w};

        #pragma unroll
        for (int j = 0; j < UNROLL; ++j)
            STEP(rows[j], wts[j], e[j]);
    }
    // Tail (NNZ multiple of 16 in practice; kept for generality).
    for (; li < lend; ++li) {
        const int   r = s_row[li];
        const int   c = s_col[li];
        const float w = s_w[li];
        const float2 e = __ldg(emb2 + (size_t)c * 32 + lane);
        STEP(r, w, e);
    }

    FLUSH();

    #undef STEP
    #undef FLUSH
}

extern "C" void kernel_launch(void* const* d_in, const int* in_sizes, int n_in,
                              void* d_out, int out_size)
{
    const int*   row_idx = (const int*)  d_in[0];
    const int*   col_idx = (const int*)  d_in[1];
    const float* data    = (const float*)d_in[2];
    const float* emb     = (const float*)d_in[4];
    float*       out     = (float*)d_out;

    const int nnz = in_sizes[0];

    cudaMemsetAsync(out, 0, (size_t)out_size * sizeof(float));

    const int blocks = (nnz + NNZ_PB - 1) / NNZ_PB;
    weighted_seg_sum_kernel<<<blocks, THREADS>>>(
        row_idx, col_idx, data, emb, out, nnz);
}